// round 1
// baseline (speedup 1.0000x reference)
#include <cuda_runtime.h>

// QLSTM closed form:
//   qgate(x, p)[:, w] = prod_{j<=w} cos(p[j,1]) * cos(x[:,j] + p[j,0])
// (product state before CNOT chain; Z_w conjugates to prod_{j<=w} Z_j; RZ is dead.)
// Then a standard LSTM cell with residual + layernorm, sequential over T only,
// independent across batch rows.

#define TT 128
#define BB 256
#define DD 64
#define HH 10
#define G4 40   // 4 gates * H

// Scratch: precomputed input projection for all (t, b): pre[t][b][g*10+w]
__device__ float g_pre[TT * BB * G4];

__device__ __forceinline__ float sig_(float z)  { return 1.f / (1.f + __expf(-z)); }
__device__ __forceinline__ float tanh_(float z) { float e = __expf(-2.f * z); return (1.f - e) / (1.f + e); }

// ---------------------------------------------------------------------------
// Kernel 1: pre[t,b,:] = b_g + x[t,b,:] @ Wg[:, :64]^T   for all 4 gates.
// 128 threads = 4 warps, one row per warp. W stored transposed in shared
// (WsT[d*40 + idx]) so lane reads are conflict-free.
// ---------------------------------------------------------------------------
__global__ void __launch_bounds__(128) k_pre(
    const float* __restrict__ x,
    const float* __restrict__ Wf, const float* __restrict__ bf,
    const float* __restrict__ Wi, const float* __restrict__ bi,
    const float* __restrict__ Wu, const float* __restrict__ bu,
    const float* __restrict__ Wo, const float* __restrict__ bo)
{
    __shared__ float WsT[DD * G4];
    __shared__ float bs[G4];
    __shared__ float xs[4][DD];

    int tid = threadIdx.x;
    for (int k = tid; k < DD * G4; k += 128) {
        int d = k / G4, idx = k % G4;
        int g = idx / HH, w = idx % HH;
        const float* Wsrc = (g == 0) ? Wf : (g == 1) ? Wi : (g == 2) ? Wu : Wo;
        WsT[k] = Wsrc[w * (DD + HH) + d];
    }
    if (tid < G4) {
        int g = tid / HH, w = tid % HH;
        const float* bsrc = (g == 0) ? bf : (g == 1) ? bi : (g == 2) ? bu : bo;
        bs[tid] = bsrc[w];
    }
    __syncthreads();

    int warp = tid >> 5, l = tid & 31;
    int row  = blockIdx.x * 4 + warp;          // row in [0, T*B)
    const float* xr = x + (size_t)row * DD;
    xs[warp][l]      = xr[l];
    xs[warp][l + 32] = xr[l + 32];
    __syncwarp();

    float a0 = bs[l];
    float a1 = (l < 8) ? bs[l + 32] : 0.f;
    #pragma unroll
    for (int d = 0; d < DD; d++) {
        float xd = xs[warp][d];
        a0 = fmaf(xd, WsT[d * G4 + l], a0);
        if (l < 8) a1 = fmaf(xd, WsT[d * G4 + l + 32], a1);
    }
    float* pr = g_pre + (size_t)row * G4;
    pr[l] = a0;
    if (l < 8) pr[l + 32] = a1;
}

// ---------------------------------------------------------------------------
// Kernel 2: sequential scan over T. One warp per batch row, 4 warps/block,
// 64 blocks. All rows independent -> no global sync.
// ---------------------------------------------------------------------------
__global__ void __launch_bounds__(128) k_scan(
    const float* __restrict__ Wf, const float* __restrict__ pf,
    const float* __restrict__ Wi, const float* __restrict__ pi,
    const float* __restrict__ Wu, const float* __restrict__ pu,
    const float* __restrict__ Wo, const float* __restrict__ po,
    const float* __restrict__ lng_, const float* __restrict__ lnb_,
    float* __restrict__ out)
{
    __shared__ float WhT[HH * G4];      // WhT[j*40 + idx] = Wg[w][64+j]
    __shared__ float th0[G4], cth1[G4]; // RX param angle, cos(RY param)
    __shared__ float lng[HH], lnb[HH];
    __shared__ float qsh[4][G4];        // per-warp per-wire q values
    __shared__ float hraw[4][HH];       // pre-layernorm h
    __shared__ float hn_sh[4][HH];      // normalized h (carry)

    int tid = threadIdx.x;
    for (int k = tid; k < HH * G4; k += 128) {
        int j = k / G4, idx = k % G4;
        int g = idx / HH, w = idx % HH;
        const float* Wsrc = (g == 0) ? Wf : (g == 1) ? Wi : (g == 2) ? Wu : Wo;
        WhT[k] = Wsrc[w * (DD + HH) + DD + j];
    }
    if (tid < G4) {
        int g = tid / HH, w = tid % HH;
        const float* ps = (g == 0) ? pf : (g == 1) ? pi : (g == 2) ? pu : po;
        th0[tid]  = ps[w * 3 + 0];
        cth1[tid] = cosf(ps[w * 3 + 1]);
    }
    if (tid < HH) { lng[tid] = lng_[tid]; lnb[tid] = lnb_[tid]; }

    int warp = tid >> 5, l = tid & 31;
    if (l < HH) hn_sh[warp][l] = 0.f;
    __syncthreads();

    int row = blockIdx.x * 4 + warp;   // batch row in [0, B)
    float creg = 0.f, hxreg = 0.f;

    for (int t = 0; t < TT; t++) {
        // --- gate pre-activations: y = pre[t,row,:] + h @ Whh^T ---
        const float* pr = g_pre + ((size_t)t * BB + row) * G4;
        float y0 = pr[l];
        float y1 = (l < 8) ? pr[l + 32] : 0.f;
        #pragma unroll
        for (int j = 0; j < HH; j++) {
            float hj = hn_sh[warp][j];
            y0 = fmaf(hj, WhT[j * G4 + l], y0);
            if (l < 8) y1 = fmaf(hj, WhT[j * G4 + l + 32], y1);
        }
        // per-wire quantum factor
        qsh[warp][l] = cth1[l] * __cosf(y0 + th0[l]);
        if (l < 8) qsh[warp][l + 32] = cth1[l + 32] * __cosf(y1 + th0[l + 32]);
        __syncwarp();

        // --- gate values (prefix products), LSTM cell ---
        if (l < HH) {
            float p0 = 1.f, p1 = 1.f, p2 = 1.f, p3 = 1.f;
            for (int j = 0; j <= l; j++) {
                p0 *= qsh[warp][j];
                p1 *= qsh[warp][HH + j];
                p2 *= qsh[warp][2 * HH + j];
                p3 *= qsh[warp][3 * HH + j];
            }
            float fg = sig_(p0), ig = sig_(p1), gg = tanh_(p2), og = sig_(p3);
            creg = fg * creg + ig * gg;
            float h = og * tanh_(creg) + hxreg;   // residual skip
            hraw[warp][l] = h;
        }
        __syncwarp();

        // --- layernorm over H=10 (two-pass, shared-memory broadcast) ---
        if (l < HH) {
            float s = 0.f;
            #pragma unroll
            for (int j = 0; j < HH; j++) s += hraw[warp][j];
            float mu = s * 0.1f;
            float s2 = 0.f;
            #pragma unroll
            for (int j = 0; j < HH; j++) { float d = hraw[warp][j] - mu; s2 = fmaf(d, d, s2); }
            float var = s2 * 0.1f;
            float hn = (hraw[warp][l] - mu) * rsqrtf(var + 1e-5f) * lng[l] + lnb[l];
            hxreg = hn;
            hn_sh[warp][l] = hn;
            out[((size_t)t * BB + row) * HH + l] = hn;
        }
        __syncwarp();
    }

    // final carries: hx == last normalized h, cx == last cell state
    if (l < HH) {
        out[(size_t)TT * BB * HH + row * HH + l]            = hxreg;
        out[(size_t)TT * BB * HH + BB * HH + row * HH + l]  = creg;
    }
}

extern "C" void kernel_launch(void* const* d_in, const int* in_sizes, int n_in,
                              void* d_out, int out_size)
{
    const float* x   = (const float*)d_in[0];
    const float* Wf  = (const float*)d_in[1];
    const float* bf  = (const float*)d_in[2];
    const float* pf  = (const float*)d_in[3];
    const float* Wi  = (const float*)d_in[4];
    const float* bi  = (const float*)d_in[5];
    const float* pi_ = (const float*)d_in[6];
    const float* Wu  = (const float*)d_in[7];
    const float* bu  = (const float*)d_in[8];
    const float* pu  = (const float*)d_in[9];
    const float* Wo  = (const float*)d_in[10];
    const float* bo  = (const float*)d_in[11];
    const float* po  = (const float*)d_in[12];
    const float* lng = (const float*)d_in[13];
    const float* lnb = (const float*)d_in[14];

    k_pre<<<(TT * BB) / 4, 128>>>(x, Wf, bf, Wi, bi, Wu, bu, Wo, bo);
    k_scan<<<BB / 4, 128>>>(Wf, pf, Wi, pi_, Wu, pu, Wo, po, lng, lnb, (float*)d_out);
}

// round 2
// speedup vs baseline: 2.4234x; 2.4234x over previous
#include <cuda_runtime.h>

// QLSTM closed form:
//   qgate(x, p)[:, w] = prod_{j<=w} cos(p[j,1]) * cos(y[:,j] + p[j,0])
// LSTM cell + residual + layernorm; sequential over T only, independent per row.

#define TT 128
#define BB 256
#define DD 64
#define HH 10
#define G4 40   // 4 gates * H

__device__ float g_pre[TT * BB * G4];

__device__ __forceinline__ float sig_(float z) {
    return __fdividef(1.f, 1.f + __expf(-z));
}
__device__ __forceinline__ float tanh_(float z) {
    float e = __expf(-2.f * z);
    return __fdividef(1.f - e, 1.f + e);
}

// ---------------------------------------------------------------------------
// Kernel 1: pre[t,b,:] = b_g + x[t,b,:] @ Wg[:, :64]^T. Warp per row, 8 rows
// per warp to amortize the shared weight staging.
// ---------------------------------------------------------------------------
#define ROWS_PER_WARP 8
__global__ void __launch_bounds__(128) k_pre(
    const float* __restrict__ x,
    const float* __restrict__ Wf, const float* __restrict__ bf,
    const float* __restrict__ Wi, const float* __restrict__ bi,
    const float* __restrict__ Wu, const float* __restrict__ bu,
    const float* __restrict__ Wo, const float* __restrict__ bo)
{
    __shared__ float WsT[DD * G4];
    __shared__ float bs[G4];
    __shared__ float xs[4][DD];

    int tid = threadIdx.x;
    for (int k = tid; k < DD * G4; k += 128) {
        int d = k / G4, idx = k % G4;
        int g = idx / HH, w = idx % HH;
        const float* Wsrc = (g == 0) ? Wf : (g == 1) ? Wi : (g == 2) ? Wu : Wo;
        WsT[k] = Wsrc[w * (DD + HH) + d];
    }
    if (tid < G4) {
        int g = tid / HH, w = tid % HH;
        const float* bsrc = (g == 0) ? bf : (g == 1) ? bi : (g == 2) ? bu : bo;
        bs[tid] = bsrc[w];
    }
    __syncthreads();

    int warp = tid >> 5, l = tid & 31;
    int base = (blockIdx.x * 4 + warp) * ROWS_PER_WARP;
    float b0 = bs[l];
    float b1 = (l < 8) ? bs[l + 32] : 0.f;

    for (int i = 0; i < ROWS_PER_WARP; i++) {
        int row = base + i;
        const float* xr = x + (size_t)row * DD;
        xs[warp][l]      = xr[l];
        xs[warp][l + 32] = xr[l + 32];
        __syncwarp();

        float a0 = b0, a0b = 0.f;
        float a1 = b1, a1b = 0.f;
        #pragma unroll
        for (int d = 0; d < DD; d += 2) {
            float xd0 = xs[warp][d], xd1 = xs[warp][d + 1];
            a0  = fmaf(xd0, WsT[d * G4 + l], a0);
            a0b = fmaf(xd1, WsT[(d + 1) * G4 + l], a0b);
            if (l < 8) {
                a1  = fmaf(xd0, WsT[d * G4 + l + 32], a1);
                a1b = fmaf(xd1, WsT[(d + 1) * G4 + l + 32], a1b);
            }
        }
        float* pr = g_pre + (size_t)row * G4;
        pr[l] = a0 + a0b;
        if (l < 8) pr[l + 32] = a1 + a1b;
        __syncwarp();
    }
}

// ---------------------------------------------------------------------------
// Kernel 2: sequential scan. One warp per batch row, 4 warps/block, 64 blocks
// (one warp per SMSP on 64 SMs). Everything register-resident except one
// 40-float q exchange per step (parity double-buffered, one __syncwarp).
// ---------------------------------------------------------------------------
__global__ void __launch_bounds__(128) k_scan(
    const float* __restrict__ Wf, const float* __restrict__ pf,
    const float* __restrict__ Wi, const float* __restrict__ pi,
    const float* __restrict__ Wu, const float* __restrict__ pu,
    const float* __restrict__ Wo, const float* __restrict__ po,
    const float* __restrict__ lng_, const float* __restrict__ lnb_,
    float* __restrict__ out)
{
    // per-warp q exchange: 4 gate segments padded to 12 floats, double-buffered
    __shared__ float qs[4][2][48];

    int tid  = threadIdx.x;
    int warp = tid >> 5, l = tid & 31;
    int row  = blockIdx.x * 4 + warp;

    // channel 0 = l (l<32): gate g0 = l/10, wire w0 = l%10
    // channel 1 = 32+l (l<8): gate 3, wire 2+l
    int g0 = l / 10, w0 = l - g0 * 10;
    const float* Wg0 = (g0 == 0) ? Wf : (g0 == 1) ? Wi : (g0 == 2) ? Wu : Wo;
    const float* Pg0 = (g0 == 0) ? pf : (g0 == 1) ? pi : (g0 == 2) ? pu : po;

    float th0_0  = Pg0[w0 * 3 + 0];
    float cth1_0 = cosf(Pg0[w0 * 3 + 1]);
    float whh0[HH];
    #pragma unroll
    for (int j = 0; j < HH; j++) whh0[j] = Wg0[w0 * (DD + HH) + DD + j];

    int w1 = 2 + l;                 // only meaningful for l<8 (gate o)
    float th0_1 = 0.f, cth1_1 = 0.f;
    float whh1[HH];
    #pragma unroll
    for (int j = 0; j < HH; j++) whh1[j] = 0.f;
    if (l < 8) {
        th0_1  = po[w1 * 3 + 0];
        cth1_1 = cosf(po[w1 * 3 + 1]);
        #pragma unroll
        for (int j = 0; j < HH; j++) whh1[j] = Wo[w1 * (DD + HH) + DD + j];
    }

    float lngr[HH], lnbr[HH];
    #pragma unroll
    for (int j = 0; j < HH; j++) { lngr[j] = lng_[j]; lnbr[j] = lnb_[j]; }

    float hj[HH];                   // broadcast normalized h (every lane)
    #pragma unroll
    for (int j = 0; j < HH; j++) hj[j] = 0.f;

    float creg = 0.f;

    // prefetch pre for t=0
    const float* prow = g_pre + (size_t)row * G4;
    float pre0 = prow[l];
    float pre1 = (l < 8) ? prow[32 + l] : 0.f;

    for (int t = 0; t < TT; t++) {
        // issue prefetch for t+1 immediately (hidden under this step's chain)
        float npre0 = 0.f, npre1 = 0.f;
        if (t + 1 < TT) {
            const float* pn = g_pre + ((size_t)(t + 1) * BB + row) * G4;
            npre0 = pn[l];
            npre1 = (l < 8) ? pn[32 + l] : 0.f;
        }

        // y = pre + h @ Whh^T  (register-only, two accumulators)
        float a0 = pre0, b0a = 0.f;
        float a1 = pre1, b1a = 0.f;
        #pragma unroll
        for (int j = 0; j < HH; j += 2) {
            a0  = fmaf(hj[j],     whh0[j],     a0);
            b0a = fmaf(hj[j + 1], whh0[j + 1], b0a);
            a1  = fmaf(hj[j],     whh1[j],     a1);
            b1a = fmaf(hj[j + 1], whh1[j + 1], b1a);
        }
        float q0 = cth1_0 * __cosf(a0 + b0a + th0_0);
        float q1 = cth1_1 * __cosf(a1 + b1a + th0_1);

        int par = t & 1;
        qs[warp][par][g0 * 12 + w0] = q0;
        if (l < 8) qs[warp][par][3 * 12 + w1] = q1;
        __syncwarp();

        float hval = 0.f;
        if (l < HH) {
            // broadcast loads of all 40 q values (conflict-free)
            float q[4][10];
            #pragma unroll
            for (int g = 0; g < 4; g++) {
                float4 va = *(const float4*)&qs[warp][par][g * 12 + 0];
                float4 vb = *(const float4*)&qs[warp][par][g * 12 + 4];
                float2 vc = *(const float2*)&qs[warp][par][g * 12 + 8];
                q[g][0] = va.x; q[g][1] = va.y; q[g][2] = va.z; q[g][3] = va.w;
                q[g][4] = vb.x; q[g][5] = vb.y; q[g][6] = vb.z; q[g][7] = vb.w;
                q[g][8] = vc.x; q[g][9] = vc.y;
            }
            // prefix products up to wire l (masked, fully unrolled; 4 gates ILP)
            float p0 = q[0][0], p1 = q[1][0], p2 = q[2][0], p3 = q[3][0];
            #pragma unroll
            for (int j = 1; j < HH; j++) {
                bool m = (l >= j);
                p0 *= m ? q[0][j] : 1.f;
                p1 *= m ? q[1][j] : 1.f;
                p2 *= m ? q[2][j] : 1.f;
                p3 *= m ? q[3][j] : 1.f;
            }
            float fg = sig_(p0), ig = sig_(p1), gg = tanh_(p2), og = sig_(p3);
            creg = fmaf(fg, creg, ig * gg);
            hval = fmaf(og, tanh_(creg), hj[l]);   // residual with prev normalized h
        }

        // gather raw h into every lane via shuffles
        float hr[HH];
        #pragma unroll
        for (int j = 0; j < HH; j++) hr[j] = __shfl_sync(0xffffffffu, hval, j);

        // layernorm (computed redundantly in every lane -> no re-broadcast)
        float s0 = (hr[0] + hr[1]) + (hr[2] + hr[3]);
        float s1 = (hr[4] + hr[5]) + (hr[6] + hr[7]);
        float mu = (s0 + s1 + (hr[8] + hr[9])) * 0.1f;
        float v0 = 0.f, v1 = 0.f;
        #pragma unroll
        for (int j = 0; j < HH; j += 2) {
            float d0 = hr[j] - mu, d1 = hr[j + 1] - mu;
            v0 = fmaf(d0, d0, v0);
            v1 = fmaf(d1, d1, v1);
        }
        float rs = rsqrtf((v0 + v1) * 0.1f + 1e-5f);
        #pragma unroll
        for (int j = 0; j < HH; j++)
            hj[j] = fmaf((hr[j] - mu) * rs, lngr[j], lnbr[j]);

        if (l < HH)
            out[((size_t)t * BB + row) * HH + l] = hj[l];

        pre0 = npre0;
        pre1 = npre1;
    }

    if (l < HH) {
        out[(size_t)TT * BB * HH + (size_t)row * HH + l]           = hj[l];
        out[(size_t)TT * BB * HH + (size_t)BB * HH + row * HH + l] = creg;
    }
}

extern "C" void kernel_launch(void* const* d_in, const int* in_sizes, int n_in,
                              void* d_out, int out_size)
{
    const float* x   = (const float*)d_in[0];
    const float* Wf  = (const float*)d_in[1];
    const float* bf  = (const float*)d_in[2];
    const float* pf  = (const float*)d_in[3];
    const float* Wi  = (const float*)d_in[4];
    const float* bi  = (const float*)d_in[5];
    const float* pi_ = (const float*)d_in[6];
    const float* Wu  = (const float*)d_in[7];
    const float* bu  = (const float*)d_in[8];
    const float* pu  = (const float*)d_in[9];
    const float* Wo  = (const float*)d_in[10];
    const float* bo  = (const float*)d_in[11];
    const float* po  = (const float*)d_in[12];
    const float* lng = (const float*)d_in[13];
    const float* lnb = (const float*)d_in[14];

    k_pre<<<(TT * BB) / (4 * ROWS_PER_WARP), 128>>>(x, Wf, bf, Wi, bi, Wu, bu, Wo, bo);
    k_scan<<<BB / 4, 128>>>(Wf, pf, Wi, pi_, Wu, pu, Wo, po, lng, lnb, (float*)d_out);
}

// round 3
// speedup vs baseline: 2.7671x; 1.1418x over previous
#include <cuda_runtime.h>

// QLSTM closed form:
//   qgate(x, p)[:, w] = prod_{j<=w} cos(p[j,1]) * cos(y[:,j] + p[j,0])
// LSTM cell + residual + layernorm; sequential over T only, independent per row.

#define TT 128
#define BB 256
#define DD 64
#define HH 10
#define G4 40   // 4 gates * H

__device__ float g_pre[TT * BB * G4];

__device__ __forceinline__ float tanh_fast(float x) {
    float y;
    asm("tanh.approx.f32 %0, %1;" : "=f"(y) : "f"(x));
    return y;
}
__device__ __forceinline__ float sig_fast(float x) {
    return fmaf(0.5f, tanh_fast(0.5f * x), 0.5f);
}

// ---------------------------------------------------------------------------
// Kernel 1: pre[t,b,:] = b_g + x[t,b,:] @ Wg[:, :64]^T. Warp per row, 8 rows
// per warp to amortize the shared weight staging.
// ---------------------------------------------------------------------------
#define ROWS_PER_WARP 8
__global__ void __launch_bounds__(128) k_pre(
    const float* __restrict__ x,
    const float* __restrict__ Wf, const float* __restrict__ bf,
    const float* __restrict__ Wi, const float* __restrict__ bi,
    const float* __restrict__ Wu, const float* __restrict__ bu,
    const float* __restrict__ Wo, const float* __restrict__ bo)
{
    __shared__ float WsT[DD * G4];
    __shared__ float bs[G4];
    __shared__ float xs[4][DD];

    int tid = threadIdx.x;
    for (int k = tid; k < DD * G4; k += 128) {
        int d = k / G4, idx = k % G4;
        int g = idx / HH, w = idx % HH;
        const float* Wsrc = (g == 0) ? Wf : (g == 1) ? Wi : (g == 2) ? Wu : Wo;
        WsT[k] = Wsrc[w * (DD + HH) + d];
    }
    if (tid < G4) {
        int g = tid / HH, w = tid % HH;
        const float* bsrc = (g == 0) ? bf : (g == 1) ? bi : (g == 2) ? bu : bo;
        bs[tid] = bsrc[w];
    }
    __syncthreads();

    int warp = tid >> 5, l = tid & 31;
    int base = (blockIdx.x * 4 + warp) * ROWS_PER_WARP;
    float b0 = bs[l];
    float b1 = (l < 8) ? bs[l + 32] : 0.f;

    for (int i = 0; i < ROWS_PER_WARP; i++) {
        int row = base + i;
        const float* xr = x + (size_t)row * DD;
        xs[warp][l]      = xr[l];
        xs[warp][l + 32] = xr[l + 32];
        __syncwarp();

        float a0 = b0, a0b = 0.f;
        float a1 = b1, a1b = 0.f;
        #pragma unroll
        for (int d = 0; d < DD; d += 2) {
            float xd0 = xs[warp][d], xd1 = xs[warp][d + 1];
            a0  = fmaf(xd0, WsT[d * G4 + l], a0);
            a0b = fmaf(xd1, WsT[(d + 1) * G4 + l], a0b);
            if (l < 8) {
                a1  = fmaf(xd0, WsT[d * G4 + l + 32], a1);
                a1b = fmaf(xd1, WsT[(d + 1) * G4 + l + 32], a1b);
            }
        }
        float* pr = g_pre + (size_t)row * G4;
        pr[l] = a0 + a0b;
        if (l < 8) pr[l + 32] = a1 + a1b;
        __syncwarp();
    }
}

// ---------------------------------------------------------------------------
// Kernel 2: sequential scan. One warp per batch row, 4 warps/block, 64 blocks.
// Carry state: zhat[10] (pre-affine normalized h, register-resident, static
// indexing only), hown (own-lane affine h), creg. LN affine folded into the
// recurrent weights and the cos() phase. One shared q-exchange per step
// (parity double buffer, single __syncwarp). tanh.approx nonlinearities.
// ---------------------------------------------------------------------------
__global__ void __launch_bounds__(128) k_scan(
    const float* __restrict__ Wf, const float* __restrict__ pf,
    const float* __restrict__ Wi, const float* __restrict__ pi,
    const float* __restrict__ Wu, const float* __restrict__ pu,
    const float* __restrict__ Wo, const float* __restrict__ po,
    const float* __restrict__ lng_, const float* __restrict__ lnb_,
    float* __restrict__ out)
{
    __shared__ float qs[4][2][48];

    int tid  = threadIdx.x;
    int warp = tid >> 5, l = tid & 31;
    int row  = blockIdx.x * 4 + warp;

    // channel 0 = l: gate g0 = l/10, wire w0 = l%10  (l=30,31 -> gate 3 wires 0,1)
    // channel 1 = 32+l (l<8): gate 3, wires 2..9
    int g0 = l / 10, w0 = l - g0 * 10;
    const float* Wg0 = (g0 == 0) ? Wf : (g0 == 1) ? Wi : (g0 == 2) ? Wu : Wo;
    const float* Pg0 = (g0 == 0) ? pf : (g0 == 1) ? pi : (g0 == 2) ? pu : po;

    // fold LN affine: y = pre + sum_j (zhat_j * (whh_j*lng_j)) + sum_j lnb_j*whh_j
    // the constant term is folded into the cos phase th0.
    float th0_0  = Pg0[w0 * 3 + 0];
    float cth1_0 = cosf(Pg0[w0 * 3 + 1]);
    float whh0[HH];
    #pragma unroll
    for (int j = 0; j < HH; j++) {
        float w = Wg0[w0 * (DD + HH) + DD + j];
        float lg = lng_[j], lb = lnb_[j];
        whh0[j] = w * lg;
        th0_0   = fmaf(lb, w, th0_0);
    }

    int w1 = 2 + l;                 // only meaningful for l<8 (gate o)
    float th0_1 = 0.f, cth1_1 = 0.f;
    float whh1[HH];
    #pragma unroll
    for (int j = 0; j < HH; j++) whh1[j] = 0.f;
    if (l < 8) {
        th0_1  = po[w1 * 3 + 0];
        cth1_1 = cosf(po[w1 * 3 + 1]);
        #pragma unroll
        for (int j = 0; j < HH; j++) {
            float w = Wo[w1 * (DD + HH) + DD + j];
            whh1[j] = w * lng_[j];
            th0_1   = fmaf(lnb_[j], w, th0_1);
        }
    }

    // own-lane LN affine params (static guard, outside loop)
    float lng_l = 0.f, lnb_l = 0.f;
    if (l < HH) { lng_l = lng_[l]; lnb_l = lnb_[l]; }

    float zhat[HH];                 // pre-affine normalized h (broadcast carry)
    #pragma unroll
    for (int j = 0; j < HH; j++) zhat[j] = 0.f;
    float hown = lnb_l * 0.f;       // affine normalized own-wire h; t=0 uses 0
    // NOTE: reference init h=0 exactly (not layernorm of 0), so carry starts 0.
    hown = 0.f;
    float creg = 0.f;

    // prefetch pre for t=0
    const float* prow = g_pre + (size_t)row * G4;
    float pre0 = prow[l];
    float pre1 = (l < 8) ? prow[32 + l] : 0.f;

    #pragma unroll 2
    for (int t = 0; t < TT; t++) {
        // prefetch t+1 (clamped, branch-free); hidden under this step's chain
        int tn = (t + 1 < TT) ? t + 1 : TT - 1;
        const float* pn = g_pre + ((size_t)tn * BB + row) * G4;
        float npre0 = pn[l];
        float npre1 = (l < 8) ? pn[32 + l] : 0.f;

        // y = pre + zhat @ whh'  (4 accumulators, depth-3 FMA)
        float a0 = pre0, a1 = 0.f, a2 = 0.f, a3 = 0.f;
        float c0 = pre1, c1 = 0.f, c2 = 0.f, c3 = 0.f;
        a0 = fmaf(zhat[0], whh0[0], a0);  c0 = fmaf(zhat[0], whh1[0], c0);
        a1 = fmaf(zhat[1], whh0[1], a1);  c1 = fmaf(zhat[1], whh1[1], c1);
        a2 = fmaf(zhat[2], whh0[2], a2);  c2 = fmaf(zhat[2], whh1[2], c2);
        a3 = fmaf(zhat[3], whh0[3], a3);  c3 = fmaf(zhat[3], whh1[3], c3);
        a0 = fmaf(zhat[4], whh0[4], a0);  c0 = fmaf(zhat[4], whh1[4], c0);
        a1 = fmaf(zhat[5], whh0[5], a1);  c1 = fmaf(zhat[5], whh1[5], c1);
        a2 = fmaf(zhat[6], whh0[6], a2);  c2 = fmaf(zhat[6], whh1[6], c2);
        a3 = fmaf(zhat[7], whh0[7], a3);  c3 = fmaf(zhat[7], whh1[7], c3);
        a0 = fmaf(zhat[8], whh0[8], a0);  c0 = fmaf(zhat[8], whh1[8], c0);
        a1 = fmaf(zhat[9], whh0[9], a1);  c1 = fmaf(zhat[9], whh1[9], c1);
        float y0 = (a0 + a1) + (a2 + a3);
        float y1 = (c0 + c1) + (c2 + c3);

        float q0 = cth1_0 * __cosf(y0 + th0_0);
        float q1 = cth1_1 * __cosf(y1 + th0_1);

        int par = t & 1;
        qs[warp][par][g0 * 12 + w0] = q0;
        if (l < 8) qs[warp][par][3 * 12 + w1] = q1;
        __syncwarp();

        // ---- gate/cell block: ALL lanes compute (no branch); lanes>=10 garbage
        float q[4][10];
        #pragma unroll
        for (int g = 0; g < 4; g++) {
            float4 va = *(const float4*)&qs[warp][par][g * 12 + 0];
            float4 vb = *(const float4*)&qs[warp][par][g * 12 + 4];
            float2 vc = *(const float2*)&qs[warp][par][g * 12 + 8];
            q[g][0] = va.x; q[g][1] = va.y; q[g][2] = va.z; q[g][3] = va.w;
            q[g][4] = vb.x; q[g][5] = vb.y; q[g][6] = vb.z; q[g][7] = vb.w;
            q[g][8] = vc.x; q[g][9] = vc.y;
        }
        // masked values (SELs independent, off-chain), then tree product
        float qm[4][10];
        #pragma unroll
        for (int g = 0; g < 4; g++) {
            qm[g][0] = q[g][0];
            #pragma unroll
            for (int j = 1; j < HH; j++)
                qm[g][j] = (l >= j) ? q[g][j] : 1.f;
        }
        float p[4];
        #pragma unroll
        for (int g = 0; g < 4; g++) {
            float m01 = qm[g][0] * qm[g][1];
            float m23 = qm[g][2] * qm[g][3];
            float m45 = qm[g][4] * qm[g][5];
            float m67 = qm[g][6] * qm[g][7];
            float m89 = qm[g][8] * qm[g][9];
            float m03 = m01 * m23;
            float m47 = m45 * m67;
            p[g] = (m03 * m47) * m89;
        }
        float fg = sig_fast(p[0]);
        float ig = sig_fast(p[1]);
        float gg = tanh_fast(p[2]);
        float og = sig_fast(p[3]);
        creg = fmaf(fg, creg, ig * gg);
        float hval = fmaf(og, tanh_fast(creg), hown);   // residual: prev affine h

        // ---- gather raw h into every lane (parallel shuffles)
        float hr[HH];
        #pragma unroll
        for (int j = 0; j < HH; j++) hr[j] = __shfl_sync(0xffffffffu, hval, j);

        // ---- layernorm stats (every lane, redundant)
        float s0 = (hr[0] + hr[1]) + (hr[2] + hr[3]);
        float s1 = (hr[4] + hr[5]) + (hr[6] + hr[7]);
        float mu = (s0 + s1 + (hr[8] + hr[9])) * 0.1f;
        float v0 = 0.f, v1 = 0.f;
        #pragma unroll
        for (int j = 0; j < HH; j += 2) {
            float d0 = hr[j] - mu, d1 = hr[j + 1] - mu;
            v0 = fmaf(d0, d0, v0);
            v1 = fmaf(d1, d1, v1);
        }
        float rs = rsqrtf((v0 + v1) * 0.1f + 1e-5f);
        #pragma unroll
        for (int j = 0; j < HH; j++)
            zhat[j] = (hr[j] - mu) * rs;                // pre-affine carry
        hown = fmaf((hval - mu) * rs, lng_l, lnb_l);    // own-lane affine h

        if (l < HH)
            out[((size_t)t * BB + row) * HH + l] = hown;

        pre0 = npre0;
        pre1 = npre1;
    }

    if (l < HH) {
        out[(size_t)TT * BB * HH + (size_t)row * HH + l]           = hown;
        out[(size_t)TT * BB * HH + (size_t)BB * HH + row * HH + l] = creg;
    }
}

extern "C" void kernel_launch(void* const* d_in, const int* in_sizes, int n_in,
                              void* d_out, int out_size)
{
    const float* x   = (const float*)d_in[0];
    const float* Wf  = (const float*)d_in[1];
    const float* bf  = (const float*)d_in[2];
    const float* pf  = (const float*)d_in[3];
    const float* Wi  = (const float*)d_in[4];
    const float* bi  = (const float*)d_in[5];
    const float* pi_ = (const float*)d_in[6];
    const float* Wu  = (const float*)d_in[7];
    const float* bu  = (const float*)d_in[8];
    const float* pu  = (const float*)d_in[9];
    const float* Wo  = (const float*)d_in[10];
    const float* bo  = (const float*)d_in[11];
    const float* po  = (const float*)d_in[12];
    const float* lng = (const float*)d_in[13];
    const float* lnb = (const float*)d_in[14];

    k_pre<<<(TT * BB) / (4 * ROWS_PER_WARP), 128>>>(x, Wf, bf, Wi, bi, Wu, bu, Wo, bo);
    k_scan<<<BB / 4, 128>>>(Wf, pf, Wi, pi_, Wu, pu, Wo, po, lng, lnb, (float*)d_out);
}

// round 4
// speedup vs baseline: 2.8581x; 1.0329x over previous
#include <cuda_runtime.h>

// QLSTM closed form:
//   qgate(x, p)[:, w] = prod_{j<=w} cos(p[j,1]) * cos(y[:,j] + p[j,0])
// LSTM cell + residual + layernorm; sequential over T only, independent per row.

#define TT 128
#define BB 256
#define DD 64
#define HH 10
#define G4 40   // 4 gates * H

// Layout: pre[row][t][ch]  (row-contiguous so each scan warp streams 20KB)
__device__ float g_pre[BB * TT * G4];

__device__ __forceinline__ float tanh_fast(float x) {
    float y;
    asm("tanh.approx.f32 %0, %1;" : "=f"(y) : "f"(x));
    return y;
}
__device__ __forceinline__ float sig_fast(float x) {
    return fmaf(0.5f, tanh_fast(0.5f * x), 0.5f);
}

// ---------------------------------------------------------------------------
// Kernel 1: pre[b][t][:] = b_g + th0 + sum_j lnb_j*Whh_j  +  x[t,b,:] @ Wg^T
// (cos phase and LN-bias recurrent term folded into the bias).
// Warp per (t,b) row, 8 rows per warp.
// ---------------------------------------------------------------------------
#define ROWS_PER_WARP 8
__global__ void __launch_bounds__(128) k_pre(
    const float* __restrict__ x,
    const float* __restrict__ Wf, const float* __restrict__ bf, const float* __restrict__ pf,
    const float* __restrict__ Wi, const float* __restrict__ bi, const float* __restrict__ pi,
    const float* __restrict__ Wu, const float* __restrict__ bu, const float* __restrict__ pu,
    const float* __restrict__ Wo, const float* __restrict__ bo, const float* __restrict__ po,
    const float* __restrict__ lnb_)
{
    __shared__ float WsT[DD * G4];
    __shared__ float bs[G4];
    __shared__ float xs[4][DD];

    int tid = threadIdx.x;
    for (int k = tid; k < DD * G4; k += 128) {
        int d = k / G4, idx = k % G4;
        int g = idx / HH, w = idx % HH;
        const float* Wsrc = (g == 0) ? Wf : (g == 1) ? Wi : (g == 2) ? Wu : Wo;
        WsT[k] = Wsrc[w * (DD + HH) + d];
    }
    if (tid < G4) {
        int g = tid / HH, w = tid % HH;
        const float* bsrc = (g == 0) ? bf : (g == 1) ? bi : (g == 2) ? bu : bo;
        const float* psrc = (g == 0) ? pf : (g == 1) ? pi : (g == 2) ? pu : po;
        const float* Wsrc = (g == 0) ? Wf : (g == 1) ? Wi : (g == 2) ? Wu : Wo;
        float acc = bsrc[w] + psrc[w * 3 + 0];          // bias + cos phase
        #pragma unroll
        for (int j = 0; j < HH; j++)                    // + lnb @ Whh
            acc = fmaf(lnb_[j], Wsrc[w * (DD + HH) + DD + j], acc);
        bs[tid] = acc;
    }
    __syncthreads();

    int warp = tid >> 5, l = tid & 31;
    int base = (blockIdx.x * 4 + warp) * ROWS_PER_WARP;
    float b0 = bs[l];
    float b1 = (l < 8) ? bs[l + 32] : 0.f;

    for (int i = 0; i < ROWS_PER_WARP; i++) {
        int row = base + i;                 // row index in [0, T*B): row = t*BB + b
        const float* xr = x + (size_t)row * DD;
        xs[warp][l]      = xr[l];
        xs[warp][l + 32] = xr[l + 32];
        __syncwarp();

        float a0 = b0, a0b = 0.f;
        float a1 = b1, a1b = 0.f;
        #pragma unroll
        for (int d = 0; d < DD; d += 2) {
            float xd0 = xs[warp][d], xd1 = xs[warp][d + 1];
            a0  = fmaf(xd0, WsT[d * G4 + l], a0);
            a0b = fmaf(xd1, WsT[(d + 1) * G4 + l], a0b);
            if (l < 8) {
                a1  = fmaf(xd0, WsT[d * G4 + l + 32], a1);
                a1b = fmaf(xd1, WsT[(d + 1) * G4 + l + 32], a1b);
            }
        }
        int t = row / BB, brow = row - t * BB;
        float* pr = g_pre + ((size_t)brow * TT + t) * G4;
        pr[l] = a0 + a0b;
        if (l < 8) pr[l + 32] = a1 + a1b;
        __syncwarp();
    }
}

// ---------------------------------------------------------------------------
// Kernel 2: sequential scan. One warp per batch row, 4 warps/block, 64 blocks.
// Depth-2 prefetch of pre-activations; rsqrt off-chain via (dm, rs) carry.
// ---------------------------------------------------------------------------
__global__ void __launch_bounds__(128) k_scan(
    const float* __restrict__ Wf, const float* __restrict__ pf,
    const float* __restrict__ Wi, const float* __restrict__ pi,
    const float* __restrict__ Wu, const float* __restrict__ pu,
    const float* __restrict__ Wo, const float* __restrict__ po,
    const float* __restrict__ lng_, const float* __restrict__ lnb_,
    float* __restrict__ out)
{
    __shared__ float qs[4][2][48];

    int tid  = threadIdx.x;
    int warp = tid >> 5, l = tid & 31;
    int row  = blockIdx.x * 4 + warp;

    // channel 0 = l: gate g0 = l/10, wire w0 = l%10
    // channel 1 = 32+l (l<8): gate 3, wires 2..9
    int g0 = l / 10, w0 = l - g0 * 10;
    const float* Wg0 = (g0 == 0) ? Wf : (g0 == 1) ? Wi : (g0 == 2) ? Wu : Wo;
    const float* Pg0 = (g0 == 0) ? pf : (g0 == 1) ? pi : (g0 == 2) ? pu : po;

    float cth1_0 = cosf(Pg0[w0 * 3 + 1]);
    float whh0[HH];                               // Whh * ln_g (LN affine folded)
    #pragma unroll
    for (int j = 0; j < HH; j++)
        whh0[j] = Wg0[w0 * (DD + HH) + DD + j] * lng_[j];

    int w1 = 2 + l;                               // only meaningful for l<8
    float cth1_1 = 0.f;
    float whh1[HH];
    #pragma unroll
    for (int j = 0; j < HH; j++) whh1[j] = 0.f;
    if (l < 8) {
        cth1_1 = cosf(po[w1 * 3 + 1]);
        #pragma unroll
        for (int j = 0; j < HH; j++)
            whh1[j] = Wo[w1 * (DD + HH) + DD + j] * lng_[j];
    }

    float lng_l = 0.f, lnb_l = 0.f;
    if (l < HH) { lng_l = lng_[l]; lnb_l = lnb_[l]; }

    float dm[HH];                                 // h_j - mu carry (broadcast)
    #pragma unroll
    for (int j = 0; j < HH; j++) dm[j] = 0.f;
    float rs   = 0.f;                             // rsqrt(var+eps); 0 at t=0 (dm=0 anyway)
    float hown = 0.f;                             // own-lane affine normalized h
    float creg = 0.f;

    const float* prow = g_pre + (size_t)row * TT * G4;

    // prefetch t=0 and t=1
    float preA0 = prow[l];
    float preA1 = (l < 8) ? prow[32 + l] : 0.f;
    float preB0 = prow[G4 + l];
    float preB1 = (l < 8) ? prow[G4 + 32 + l] : 0.f;

    #pragma unroll 2
    for (int t = 0; t < TT; t++) {
        // prefetch t+2 (clamped) — two full steps of slack over L2 latency
        int tn = (t + 2 < TT) ? t + 2 : TT - 1;
        const float* pn = prow + (size_t)tn * G4;
        float preC0 = pn[l];
        float preC1 = (l < 8) ? pn[32 + l] : 0.f;

        // dot = dm @ whh' ; y = pre' + rs*dot  (rsqrt already resolved off-chain)
        float a0 = 0.f, a1 = 0.f, a2 = 0.f, a3 = 0.f;
        float c0 = 0.f, c1 = 0.f, c2 = 0.f, c3 = 0.f;
        a0 = fmaf(dm[0], whh0[0], a0);  c0 = fmaf(dm[0], whh1[0], c0);
        a1 = fmaf(dm[1], whh0[1], a1);  c1 = fmaf(dm[1], whh1[1], c1);
        a2 = fmaf(dm[2], whh0[2], a2);  c2 = fmaf(dm[2], whh1[2], c2);
        a3 = fmaf(dm[3], whh0[3], a3);  c3 = fmaf(dm[3], whh1[3], c3);
        a0 = fmaf(dm[4], whh0[4], a0);  c0 = fmaf(dm[4], whh1[4], c0);
        a1 = fmaf(dm[5], whh0[5], a1);  c1 = fmaf(dm[5], whh1[5], c1);
        a2 = fmaf(dm[6], whh0[6], a2);  c2 = fmaf(dm[6], whh1[6], c2);
        a3 = fmaf(dm[7], whh0[7], a3);  c3 = fmaf(dm[7], whh1[7], c3);
        a0 = fmaf(dm[8], whh0[8], a0);  c0 = fmaf(dm[8], whh1[8], c0);
        a1 = fmaf(dm[9], whh0[9], a1);  c1 = fmaf(dm[9], whh1[9], c1);
        float y0 = fmaf(rs, (a0 + a1) + (a2 + a3), preA0);
        float y1 = fmaf(rs, (c0 + c1) + (c2 + c3), preA1);

        float q0 = cth1_0 * __cosf(y0);
        float q1 = cth1_1 * __cosf(y1);

        int par = t & 1;
        qs[warp][par][g0 * 12 + w0] = q0;
        if (l < 8) qs[warp][par][3 * 12 + w1] = q1;
        __syncwarp();

        // all lanes compute gate/cell redundantly (lanes>=10 garbage, harmless)
        float q[4][10];
        #pragma unroll
        for (int g = 0; g < 4; g++) {
            float4 va = *(const float4*)&qs[warp][par][g * 12 + 0];
            float4 vb = *(const float4*)&qs[warp][par][g * 12 + 4];
            float2 vc = *(const float2*)&qs[warp][par][g * 12 + 8];
            q[g][0] = va.x; q[g][1] = va.y; q[g][2] = va.z; q[g][3] = va.w;
            q[g][4] = vb.x; q[g][5] = vb.y; q[g][6] = vb.z; q[g][7] = vb.w;
            q[g][8] = vc.x; q[g][9] = vc.y;
        }
        float qm[4][10];
        #pragma unroll
        for (int g = 0; g < 4; g++) {
            qm[g][0] = q[g][0];
            #pragma unroll
            for (int j = 1; j < HH; j++)
                qm[g][j] = (l >= j) ? q[g][j] : 1.f;
        }
        float p[4];
        #pragma unroll
        for (int g = 0; g < 4; g++) {
            float m01 = qm[g][0] * qm[g][1];
            float m23 = qm[g][2] * qm[g][3];
            float m45 = qm[g][4] * qm[g][5];
            float m67 = qm[g][6] * qm[g][7];
            float m89 = qm[g][8] * qm[g][9];
            p[g] = ((m01 * m23) * (m45 * m67)) * m89;
        }
        float fg = sig_fast(p[0]);
        float ig = sig_fast(p[1]);
        float gg = tanh_fast(p[2]);
        float og = sig_fast(p[3]);
        creg = fmaf(fg, creg, ig * gg);
        float hval = fmaf(og, tanh_fast(creg), hown);   // residual: prev affine h

        // gather raw h into every lane
        float hr[HH];
        #pragma unroll
        for (int j = 0; j < HH; j++) hr[j] = __shfl_sync(0xffffffffu, hval, j);

        // LN: mean first, dm carry; rsqrt resolves off-chain before next y-fma
        float s0 = (hr[0] + hr[1]) + (hr[2] + hr[3]);
        float s1 = (hr[4] + hr[5]) + (hr[6] + hr[7]);
        float mu = (s0 + s1 + (hr[8] + hr[9])) * 0.1f;
        #pragma unroll
        for (int j = 0; j < HH; j++) dm[j] = hr[j] - mu;
        float v0 = 0.f, v1 = 0.f;
        #pragma unroll
        for (int j = 0; j < HH; j += 2) {
            v0 = fmaf(dm[j],     dm[j],     v0);
            v1 = fmaf(dm[j + 1], dm[j + 1], v1);
        }
        rs   = rsqrtf((v0 + v1) * 0.1f + 1e-5f);
        hown = fmaf((hval - mu) * rs, lng_l, lnb_l);

        if (l < HH)
            out[((size_t)t * BB + row) * HH + l] = hown;

        preA0 = preB0; preA1 = preB1;
        preB0 = preC0; preB1 = preC1;
    }

    if (l < HH) {
        out[(size_t)TT * BB * HH + (size_t)row * HH + l]           = hown;
        out[(size_t)TT * BB * HH + (size_t)BB * HH + row * HH + l] = creg;
    }
}

extern "C" void kernel_launch(void* const* d_in, const int* in_sizes, int n_in,
                              void* d_out, int out_size)
{
    const float* x   = (const float*)d_in[0];
    const float* Wf  = (const float*)d_in[1];
    const float* bf  = (const float*)d_in[2];
    const float* pf  = (const float*)d_in[3];
    const float* Wi  = (const float*)d_in[4];
    const float* bi  = (const float*)d_in[5];
    const float* pi_ = (const float*)d_in[6];
    const float* Wu  = (const float*)d_in[7];
    const float* bu  = (const float*)d_in[8];
    const float* pu  = (const float*)d_in[9];
    const float* Wo  = (const float*)d_in[10];
    const float* bo  = (const float*)d_in[11];
    const float* po  = (const float*)d_in[12];
    const float* lng = (const float*)d_in[13];
    const float* lnb = (const float*)d_in[14];

    k_pre<<<(TT * BB) / (4 * ROWS_PER_WARP), 128>>>(
        x, Wf, bf, pf, Wi, bi, pi_, Wu, bu, pu, Wo, bo, po, lnb);
    k_scan<<<BB / 4, 128>>>(Wf, pf, Wi, pi_, Wu, pu, Wo, po, lng, lnb, (float*)d_out);
}